// round 10
// baseline (speedup 1.0000x reference)
#include <cuda_runtime.h>

#define CCH 32
#define HH  256
#define WW  512
#define KK  10
#define HWPIX (HH*WW)

// Transposed [H,W,C] copies (channels contiguous) — static scratch.
__device__ float g_left_t [HWPIX * CCH];
__device__ float g_right_t[HWPIX * CCH];

// [C,H,W] -> [H,W,C], float4 on both global sides. grid.z selects tensor.
__global__ __launch_bounds__(1024) void transpose_chw_hwc(
    const float* __restrict__ left, const float* __restrict__ right) {
    __shared__ float tile[32][129];
    const float* src = blockIdx.z ? right : left;
    float* dst = blockIdx.z ? g_right_t : g_left_t;
    const int h  = blockIdx.y;
    const int w0 = blockIdx.x * 128;
    const int tx = threadIdx.x, ty = threadIdx.y;

    const float4 v = *(const float4*)(src + (size_t)ty * HWPIX + h * WW + w0 + 4 * tx);
    tile[ty][4*tx + 0] = v.x;
    tile[ty][4*tx + 1] = v.y;
    tile[ty][4*tx + 2] = v.z;
    tile[ty][4*tx + 3] = v.w;
    __syncthreads();

    const int t  = ty * 32 + tx;
    const int wl = t >> 3;
    const int cq = t & 7;
    float4 o;
    o.x = tile[4*cq + 0][wl];
    o.y = tile[4*cq + 1][wl];
    o.z = tile[4*cq + 2][wl];
    o.w = tile[4*cq + 3][wl];
    *(float4*)(dst + (size_t)(h * WW + w0 + wl) * CCH + 4 * cq) = o;
}

// Broadcast offset plane p (0..9 = ox[k], 10..19 = oy[k]) within 8-lane group.
#define BCAST(p) __shfl_sync(0xffffffffu, ((p) < 8 ? o0 : ((p) < 16 ? o1 : o2)), \
                             (lane & 24) | ((p) & 7))

__global__ __launch_bounds__(256, 6) void eval_kernel(
    const float* __restrict__ offx,
    const float* __restrict__ offy,
    float* __restrict__ out)
{
    // [warp][pixel-in-warp][k] : (s, ox, oy, pad)
    __shared__ float4 s_sm[8 * 4 * KK];

    const int lane = threadIdx.x & 31;
    const int j    = lane & 7;
    const int g    = lane >> 3;
    const int warp = threadIdx.x >> 5;
    const int pix  = blockIdx.x * 32 + warp * 4 + g;
    const int h = pix >> 9;
    const int w = pix & (WW - 1);

    // left channels 4j..4j+3 — single 128B-line load from transposed layout
    const float4 lv = *(const float4*)(g_left_t + (size_t)pix * CCH + 4 * j);

    // 20 offset planes distributed over the 8-lane group
    const float o0 = offx[j * HWPIX + pix];
    const float o1 = (j < 2) ? offx[(j + 8) * HWPIX + pix]
                             : offy[(j - 2) * HWPIX + pix];
    const float o2 = (j < 4) ? offy[(j + 6) * HWPIX + pix] : 0.0f;

    const float4* __restrict__ rt = (const float4*)g_right_t;
    const float hf = (float)HH;
    const float wfl = (float)w, hfl = (float)h;

    #pragma unroll
    for (int k = 0; k < KK; k++) {
        const float ox_k = BCAST(k);
        const float oy_k = BCAST(k + KK);

        // clip->normalize->unnormalize == r-0.5 exactly in fp32;
        // offset_x >= 0 so the upper x-clamp is a no-op.
        const float rx = fmaxf(wfl - ox_k, 0.0f);
        const float ry = fminf(fmaxf(hfl - oy_k, 0.0f), hf - 1.0f);
        const float ix = rx - 0.5f;
        const float iy = ry - 0.5f;

        const float x0f = floorf(ix), y0f = floorf(iy);
        const int x0 = (int)x0f, y0 = (int)y0f;      // >= -1
        const float wx1 = ix - x0f;
        const float wy1 = iy - y0f;
        float wx0 = 1.0f - wx1;
        float wy0 = 1.0f - wy1;
        if (x0 < 0) wx0 = 0.0f;                      // only low edge can be invalid
        if (y0 < 0) wy0 = 0.0f;
        const int x0c = max(x0, 0);
        const int y0c = max(y0, 0);
        const int x1 = x0 + 1, y1 = y0 + 1;          // always in range

        const float w00 = wx0 * wy0, w01 = wx1 * wy0;
        const float w10 = wx0 * wy1, w11 = wx1 * wy1;

        // 4 independent address chains, 128B line each
        const float4 g00 = rt[(y0c * WW + x0c) * 8 + j];
        const float4 g01 = rt[(y0c * WW + x1 ) * 8 + j];
        const float4 g10 = rt[(y1  * WW + x0c) * 8 + j];
        const float4 g11 = rt[(y1  * WW + x1 ) * 8 + j];

        float d;
        {
            float t0 = w00*g00.x + w01*g01.x + w10*g10.x + w11*g11.x;
            float t1 = w00*g00.y + w01*g01.y + w10*g10.y + w11*g11.y;
            float t2 = w00*g00.z + w01*g01.z + w10*g10.z + w11*g11.z;
            float t3 = w00*g00.w + w01*g01.w + w10*g10.w + w11*g11.w;
            d = fabsf(lv.x - t0) + fabsf(lv.y - t1)
              + fabsf(lv.z - t2) + fabsf(lv.w - t3);
        }

        d += __shfl_xor_sync(0xffffffffu, d, 4);
        d += __shfl_xor_sync(0xffffffffu, d, 2);
        d += __shfl_xor_sync(0xffffffffu, d, 1);

        if (j == 0)
            s_sm[warp * (4 * KK) + g * KK + k] =
                make_float4(d * (-10000.0f / 32.0f), ox_k, oy_k, 0.0f);
    }

    __syncwarp();

    // epilogue: lane l (< 4) owns pixel (base + l) entirely
    if (lane < 4) {
        float4 v[KK];
        #pragma unroll
        for (int k = 0; k < KK; k++)
            v[k] = s_sm[warp * (4 * KK) + lane * KK + k];

        float m = v[0].x;
        #pragma unroll
        for (int k = 1; k < KK; k++) m = fmaxf(m, v[k].x);
        float denom = 0.0f, oxa = 0.0f, oya = 0.0f;
        #pragma unroll
        for (int k = 0; k < KK; k++) {
            const float e = __expf(v[k].x - m);
            denom += e;
            oxa   += e * v[k].y;
            oya   += e * v[k].z;
        }
        const float inv = 1.0f / denom;
        const int opix = blockIdx.x * 32 + warp * 4 + lane;
        out[opix]         = oxa * inv;
        out[HWPIX + opix] = oya * inv;
    }
}

extern "C" void kernel_launch(void* const* d_in, const int* in_sizes, int n_in,
                              void* d_out, int out_size) {
    const float* left  = (const float*)d_in[0];
    const float* right = (const float*)d_in[1];
    const float* offx  = (const float*)d_in[2];
    const float* offy  = (const float*)d_in[3];
    float* out = (float*)d_out;

    dim3 tb(32, 32);
    dim3 tg(WW / 128, HH, 2);
    transpose_chw_hwc<<<tg, tb>>>(left, right);

    eval_kernel<<<HWPIX / 32, 256>>>(offx, offy, out);
}

// round 12
// speedup vs baseline: 1.0491x; 1.0491x over previous
#include <cuda_runtime.h>

#define CCH 32
#define HH  256
#define WW  512
#define KK  10
#define HWPIX (HH*WW)

// Transposed [H,W,C] copy of right (channels contiguous) — static scratch.
__device__ float g_right_t[HWPIX * CCH];

// [C,H,W] -> [H,W,C], float4 on both global sides.
__global__ __launch_bounds__(1024) void transpose_chw_hwc(const float* __restrict__ right) {
    __shared__ float tile[32][129];
    const int h  = blockIdx.y;
    const int w0 = blockIdx.x * 128;
    const int tx = threadIdx.x, ty = threadIdx.y;

    const float4 v = *(const float4*)(right + (size_t)ty * HWPIX + h * WW + w0 + 4 * tx);
    tile[ty][4*tx + 0] = v.x;
    tile[ty][4*tx + 1] = v.y;
    tile[ty][4*tx + 2] = v.z;
    tile[ty][4*tx + 3] = v.w;
    __syncthreads();

    const int t  = ty * 32 + tx;
    const int wl = t >> 3;
    const int cq = t & 7;
    float4 o;
    o.x = tile[4*cq + 0][wl];
    o.y = tile[4*cq + 1][wl];
    o.z = tile[4*cq + 2][wl];
    o.w = tile[4*cq + 3][wl];
    *(float4*)(g_right_t + (size_t)(h * WW + w0 + wl) * CCH + 4 * cq) = o;
}

// Runtime-p broadcast of offset plane p (0..9 = ox[k], 10..19 = oy[k]) within
// the 8-lane group. p is warp-uniform; selects are branch-free.
__device__ __forceinline__ float bcast_off(float o0, float o1, float o2,
                                           int lane, int p) {
    const float v = (p < 8) ? o0 : ((p < 16) ? o1 : o2);
    return __shfl_sync(0xffffffffu, v, (lane & 24) | (p & 7));
}

__global__ __launch_bounds__(256, 6) void eval_kernel(
    const float* __restrict__ left,
    const float* __restrict__ offx,
    const float* __restrict__ offy,
    float* __restrict__ out)
{
    // [warp][pixel-in-warp][k] : (s, ox, oy, pad)
    __shared__ float4 s_sm[8 * 4 * KK];

    const int lane = threadIdx.x & 31;
    const int j    = lane & 7;
    const int g    = lane >> 3;
    const int warp = threadIdx.x >> 5;
    const int pix  = blockIdx.x * 32 + warp * 4 + g;
    const int h = pix >> 9;
    const int w = pix & (WW - 1);

    // left channels 4j..4j+3 (strided scalar loads from original [C,H,W])
    const float lv0 = left[(4*j + 0) * HWPIX + pix];
    const float lv1 = left[(4*j + 1) * HWPIX + pix];
    const float lv2 = left[(4*j + 2) * HWPIX + pix];
    const float lv3 = left[(4*j + 3) * HWPIX + pix];

    // 20 offset planes distributed over the 8-lane group
    const float o0 = offx[j * HWPIX + pix];
    const float o1 = (j < 2) ? offx[(j + 8) * HWPIX + pix]
                             : offy[(j - 2) * HWPIX + pix];
    const float o2 = (j < 4) ? offy[(j + 6) * HWPIX + pix] : 0.0f;

    const float4* __restrict__ rt = (const float4*)g_right_t;
    const float hf = (float)HH;
    const float wfl = (float)w, hfl = (float)h;

    // ROLLED (unroll 2) to bound the front-batched LDG count (MLP_p1) and
    // avoid the cross-CTA L1tex-queue spread. smem epilogue makes this
    // possible without an indexed register array.
    #pragma unroll 2
    for (int k = 0; k < KK; k++) {
        const float ox_k = bcast_off(o0, o1, o2, lane, k);
        const float oy_k = bcast_off(o0, o1, o2, lane, k + KK);

        // clip->normalize->unnormalize == r-0.5 exactly in fp32;
        // offset_x >= 0 so the upper x-clamp is a no-op.
        const float rx = fmaxf(wfl - ox_k, 0.0f);
        const float ry = fminf(fmaxf(hfl - oy_k, 0.0f), hf - 1.0f);
        const float ix = rx - 0.5f;
        const float iy = ry - 0.5f;

        const float x0f = floorf(ix), y0f = floorf(iy);
        const int x0 = (int)x0f, y0 = (int)y0f;      // >= -1
        const float wx1 = ix - x0f;
        const float wy1 = iy - y0f;
        float wx0 = 1.0f - wx1;
        float wy0 = 1.0f - wy1;
        if (x0 < 0) wx0 = 0.0f;                      // only low edge can be invalid
        if (y0 < 0) wy0 = 0.0f;
        const int x0c = max(x0, 0);
        const int y0c = max(y0, 0);
        const int x1 = x0 + 1, y1 = y0 + 1;          // always in range

        const float w00 = wx0 * wy0, w01 = wx1 * wy0;
        const float w10 = wx0 * wy1, w11 = wx1 * wy1;

        // 4 independent address chains, one 128B line each
        const float4 g00 = rt[(y0c * WW + x0c) * 8 + j];
        const float4 g01 = rt[(y0c * WW + x1 ) * 8 + j];
        const float4 g10 = rt[(y1  * WW + x0c) * 8 + j];
        const float4 g11 = rt[(y1  * WW + x1 ) * 8 + j];

        float d;
        {
            float t0 = w00*g00.x + w01*g01.x + w10*g10.x + w11*g11.x;
            float t1 = w00*g00.y + w01*g01.y + w10*g10.y + w11*g11.y;
            float t2 = w00*g00.z + w01*g01.z + w10*g10.z + w11*g11.z;
            float t3 = w00*g00.w + w01*g01.w + w10*g10.w + w11*g11.w;
            d = fabsf(lv0 - t0) + fabsf(lv1 - t1)
              + fabsf(lv2 - t2) + fabsf(lv3 - t3);
        }

        d += __shfl_xor_sync(0xffffffffu, d, 4);
        d += __shfl_xor_sync(0xffffffffu, d, 2);
        d += __shfl_xor_sync(0xffffffffu, d, 1);

        if (j == 0)
            s_sm[warp * (4 * KK) + g * KK + k] =
                make_float4(d * (-10000.0f / 32.0f), ox_k, oy_k, 0.0f);
    }

    __syncwarp();

    // epilogue: lane l (< 4) owns pixel (base + l) entirely
    if (lane < 4) {
        float4 v[KK];
        #pragma unroll
        for (int k = 0; k < KK; k++)
            v[k] = s_sm[warp * (4 * KK) + lane * KK + k];

        float m = v[0].x;
        #pragma unroll
        for (int k = 1; k < KK; k++) m = fmaxf(m, v[k].x);
        float denom = 0.0f, oxa = 0.0f, oya = 0.0f;
        #pragma unroll
        for (int k = 0; k < KK; k++) {
            const float e = __expf(v[k].x - m);
            denom += e;
            oxa   += e * v[k].y;
            oya   += e * v[k].z;
        }
        const float inv = 1.0f / denom;
        const int opix = blockIdx.x * 32 + warp * 4 + lane;
        out[opix]         = oxa * inv;
        out[HWPIX + opix] = oya * inv;
    }
}

extern "C" void kernel_launch(void* const* d_in, const int* in_sizes, int n_in,
                              void* d_out, int out_size) {
    const float* left  = (const float*)d_in[0];
    const float* right = (const float*)d_in[1];
    const float* offx  = (const float*)d_in[2];
    const float* offy  = (const float*)d_in[3];
    float* out = (float*)d_out;

    dim3 tb(32, 32);
    dim3 tg(WW / 128, HH);
    transpose_chw_hwc<<<tg, tb>>>(right);

    eval_kernel<<<HWPIX / 32, 256>>>(left, offx, offy, out);
}